// round 14
// baseline (speedup 1.0000x reference)
#include <cuda_runtime.h>
#include <cuda_bf16.h>
#include <math.h>
#include <stdint.h>

#define BATCH 16384
#define NTAB  26
#define NROWSZ 100000
#define EMBD  128
#define ZDIM  512   // 479 padded to 512 (pad columns zeroed)

typedef __nv_bfloat16 bf16;

// ---------------- scratch (device globals: allocation-free) ----------------
__device__ bf16 g_x512[BATCH * 512];
__device__ bf16 g_x256[BATCH * 256];
__device__ bf16 g_x128[BATCH * 128];
__device__ bf16 g_z   [BATCH * ZDIM];
__device__ bf16 g_h1  [BATCH * 1024];
__device__ bf16 g_h2  [BATCH * 1024];
__device__ bf16 g_h3  [BATCH * 512];
// bf16 weights
__device__ bf16 g_bw1 [256 * 512];
__device__ bf16 g_bw2 [128 * 256];
__device__ bf16 g_w0  [1024 * ZDIM];   // tw0 padded 479 -> 512
__device__ bf16 g_w1  [1024 * 1024];
__device__ bf16 g_w2  [512 * 1024];
__device__ bf16 g_w3  [256 * 512];
__device__ bf16 g_w4  [256];

// ======================= PTX helpers =======================
__device__ __forceinline__ uint32_t smem_u32(const void* p) {
    uint32_t a;
    asm("{ .reg .u64 t; cvta.to.shared.u64 t, %1; cvt.u32.u64 %0, t; }" : "=r"(a) : "l"(p));
    return a;
}
__device__ __forceinline__ void cpa16(uint32_t dst, const void* src) {
    asm volatile("cp.async.cg.shared.global [%0], [%1], 16;" :: "r"(dst), "l"(src) : "memory");
}
__device__ __forceinline__ void cpa_commit() {
    asm volatile("cp.async.commit_group;" ::: "memory");
}
template <int N>
__device__ __forceinline__ void cpa_wait() {
    asm volatile("cp.async.wait_group %0;" :: "n"(N) : "memory");
}
__device__ __forceinline__ uint32_t pack_bf16x2(float lo, float hi) {
    uint32_t r;
    asm("cvt.rn.bf16x2.f32 %0, %1, %2;" : "=r"(r) : "f"(hi), "f"(lo));
    return r;
}
#define LDSM4(r0, r1, r2, r3, addr)                                            \
    asm volatile("ldmatrix.sync.aligned.m8n8.x4.shared.b16 {%0,%1,%2,%3}, [%4];" \
                 : "=r"(r0), "=r"(r1), "=r"(r2), "=r"(r3) : "r"(addr))
#define LDSM2(r0, r1, addr)                                                    \
    asm volatile("ldmatrix.sync.aligned.m8n8.x2.shared.b16 {%0,%1}, [%2];"     \
                 : "=r"(r0), "=r"(r1) : "r"(addr))
#define HMMA16(d, a0, a1, a2, a3, b0, b1)                                      \
    asm volatile(                                                              \
        "mma.sync.aligned.m16n8k16.row.col.f32.bf16.bf16.f32 "                 \
        "{%0,%1,%2,%3}, {%4,%5,%6,%7}, {%8,%9}, {%0,%1,%2,%3};"                \
        : "+f"((d)[0]), "+f"((d)[1]), "+f"((d)[2]), "+f"((d)[3])               \
        : "r"(a0), "r"(a1), "r"(a2), "r"(a3), "r"(b0), "r"(b1))

// ======================= bf16 mma.sync GEMM =======================
// C(bf16) = relu(A[M,K] @ W[N,K]^T + bias(fp32)), fp32 accumulate.
// Block (TM*64)x128, 8 warps (4M x 2N), warp tile (TM*16)x64 via m16n8k16.
// K-chunk = 64 bf16 = 128B rows, XOR swizzle u^(r&7). NSTG=3.
// TM=1 (BM=64) measured 394 TF/s vs TM=2's 347 (R13: tensor 31.8% vs 17.6%)
// -> all layers use TM=1 with >=512 CTAs.
// FUSE: epilogue computes partial dot with w4 -> atomicAdd(outv) (top3+top4).
#define NSTG 3

template <int K, int TM, bool FUSE>
__global__ __launch_bounds__(256, 2)
void gemm_bf16(const bf16* __restrict__ A, const bf16* __restrict__ W,
               const float* __restrict__ bias, bf16* __restrict__ C,
               int N, float* __restrict__ outv, const bf16* __restrict__ w4v) {
    constexpr int A_BYTES = TM * 8192;         // A stage bytes
    constexpr int STG = A_BYTES + 16384;       // stage total
    extern __shared__ char smraw[];
    const uint32_t smb = smem_u32(smraw);

    const int tid  = threadIdx.x;
    const int lane = tid & 31;
    const int warp = tid >> 5;
    const int bm = blockIdx.y * (TM * 64);
    const int bn = blockIdx.x * 128;
    const int wm = (warp & 3) * (TM * 16);
    const int wn = (warp >> 2) * 64;

    float acc[TM][8][4];
#pragma unroll
    for (int t = 0; t < TM; t++)
#pragma unroll
        for (int u = 0; u < 8; u++)
#pragma unroll
            for (int v = 0; v < 4; v++) acc[t][u][v] = 0.0f;

    // ldmatrix per-warp address constants
    int ra[TM], rxa[TM];
#pragma unroll
    for (int t = 0; t < TM; t++) {
        int row = wm + t * 16 + ((lane >> 3) & 1) * 8 + (lane & 7);
        ra[t]  = row * 128;
        rxa[t] = (row & 7) << 4;
    }
    const int ua = lane >> 4;
    int rb[4], rxb[4];
#pragma unroll
    for (int g = 0; g < 4; g++) {
        int row = wn + g * 16 + ((lane >> 4) & 1) * 8 + (lane & 7);
        rb[g]  = row * 128;
        rxb[g] = (row & 7) << 4;
    }
    const int ub = (lane >> 3) & 1;

    constexpr int NC = K >> 6;

    // loader bases (thread-fixed); slices at constant strides.
    // 8 threads (u0=0..7) cover one full 128B row per cp.async -> coalesced.
    const int r0 = tid >> 3, u0 = tid & 7;
    const bf16* aP = A + (size_t)(bm + r0) * K + u0 * 8;
    const bf16* wP = W + (size_t)(bn + r0) * K + u0 * 8;
    const uint32_t dOff = smb + (uint32_t)(r0 * 128) + (uint32_t)(((u0 ^ (r0 & 7)) << 4));

    auto issue = [&](uint32_t so, const bf16* a, const bf16* w) {
#pragma unroll
        for (int i = 0; i < 2 * TM; i++) cpa16(dOff + so + i * 4096, a + i * (32 * K));
#pragma unroll
        for (int i = 0; i < 4; i++) cpa16(dOff + so + (uint32_t)A_BYTES + i * 4096, w + i * (32 * K));
        cpa_commit();
    };

    issue(0, aP, wP);
    if (NC > 1) issue(STG, aP + 64, wP + 64); else cpa_commit();
    const bf16* aN = aP + 128;
    const bf16* wN = wP + 128;
    uint32_t soN = 2 * STG;
    uint32_t soC = 0;

    uint32_t afr[2][TM][4];
    uint32_t bfr[2][4][4];

#pragma unroll 1
    for (int c = 0; c < NC; c++) {
        cpa_wait<1>();
        __syncthreads();

        const uint32_t Ab = smb + soC;
        const uint32_t Bb = Ab + (uint32_t)A_BYTES;
        soC += STG; if (soC == NSTG * STG) soC = 0;

        // prefetch ks=0 fragments FIRST (critical path), then prefetch gmem
#pragma unroll
        for (int t = 0; t < TM; t++)
            LDSM4(afr[0][t][0], afr[0][t][1], afr[0][t][2], afr[0][t][3],
                  Ab + ra[t] + (((ua) << 4) ^ rxa[t]));
#pragma unroll
        for (int g = 0; g < 4; g++)
            LDSM4(bfr[0][g][0], bfr[0][g][1], bfr[0][g][2], bfr[0][g][3],
                  Bb + rb[g] + (((ub) << 4) ^ rxb[g]));

        if (c + 2 < NC) {
            issue(soN, aN, wN);
            aN += 64; wN += 64;
            soN += STG; if (soN == NSTG * STG) soN = 0;
        } else {
            cpa_commit();
        }

#pragma unroll
        for (int ks = 0; ks < 4; ks++) {
            const int cur = ks & 1, nxt = cur ^ 1;
            if (ks < 3) {
#pragma unroll
                for (int t = 0; t < TM; t++)
                    LDSM4(afr[nxt][t][0], afr[nxt][t][1], afr[nxt][t][2], afr[nxt][t][3],
                          Ab + ra[t] + ((((ks + 1) * 2 + ua) << 4) ^ rxa[t]));
#pragma unroll
                for (int g = 0; g < 4; g++)
                    LDSM4(bfr[nxt][g][0], bfr[nxt][g][1], bfr[nxt][g][2], bfr[nxt][g][3],
                          Bb + rb[g] + ((((ks + 1) * 2 + ub) << 4) ^ rxb[g]));
            }
#pragma unroll
            for (int g = 0; g < 4; g++)
#pragma unroll
                for (int t = 0; t < TM; t++) {
                    HMMA16(acc[t][2 * g],
                           afr[cur][t][0], afr[cur][t][1], afr[cur][t][2], afr[cur][t][3],
                           bfr[cur][g][0], bfr[cur][g][1]);
                    HMMA16(acc[t][2 * g + 1],
                           afr[cur][t][0], afr[cur][t][1], afr[cur][t][2], afr[cur][t][3],
                           bfr[cur][g][2], bfr[cur][g][3]);
                }
        }
    }

    if constexpr (FUSE) {
        // fused final dot: p[row] += sum_col relu(acc+bias)*w4[col]; TM==1
        float p0 = 0.0f, p1 = 0.0f;
#pragma unroll
        for (int u = 0; u < 8; u++) {
            const int col = bn + wn + u * 8 + (lane & 3) * 2;
            const float b0v = bias[col], b1v = bias[col + 1];
            const float w0 = __bfloat162float(w4v[col]);
            const float w1 = __bfloat162float(w4v[col + 1]);
            p0 = fmaf(fmaxf(acc[0][u][0] + b0v, 0.0f), w0, p0);
            p0 = fmaf(fmaxf(acc[0][u][1] + b1v, 0.0f), w1, p0);
            p1 = fmaf(fmaxf(acc[0][u][2] + b0v, 0.0f), w0, p1);
            p1 = fmaf(fmaxf(acc[0][u][3] + b1v, 0.0f), w1, p1);
        }
        p0 += __shfl_xor_sync(0xffffffffu, p0, 1);
        p0 += __shfl_xor_sync(0xffffffffu, p0, 2);
        p1 += __shfl_xor_sync(0xffffffffu, p1, 1);
        p1 += __shfl_xor_sync(0xffffffffu, p1, 2);
        if ((lane & 3) == 0) {
            const int row = bm + wm + (lane >> 2);
            atomicAdd(&outv[row], p0);
            atomicAdd(&outv[row + 8], p1);
        }
    } else {
        // epilogue: bias + relu -> bf16
#pragma unroll
        for (int t = 0; t < TM; t++) {
            const int row = bm + wm + t * 16 + (lane >> 2);
#pragma unroll
            for (int u = 0; u < 8; u++) {
                const int col = bn + wn + u * 8 + (lane & 3) * 2;
                const float b0v = bias[col], b1v = bias[col + 1];
                uint32_t o0 = pack_bf16x2(fmaxf(acc[t][u][0] + b0v, 0.0f),
                                          fmaxf(acc[t][u][1] + b1v, 0.0f));
                uint32_t o1 = pack_bf16x2(fmaxf(acc[t][u][2] + b0v, 0.0f),
                                          fmaxf(acc[t][u][3] + b1v, 0.0f));
                *reinterpret_cast<uint32_t*>(&C[(size_t)row * N + col]) = o0;
                *reinterpret_cast<uint32_t*>(&C[(size_t)(row + 8) * N + col]) = o1;
            }
        }
    }
}

// ---------------- fused weight prep (ONE launch) ----------------
#define SZ_W0  (1024 * ZDIM)
#define SZ_BW1 (256 * 512)
#define SZ_BW2 (128 * 256)
#define SZ_W1  (1024 * 1024)
#define SZ_W2  (512 * 1024)
#define SZ_W3  (256 * 512)
#define SZ_W4  (256)
#define SZ_ALL (SZ_W0 + SZ_BW1 + SZ_BW2 + SZ_W1 + SZ_W2 + SZ_W3 + SZ_W4)

__global__ void prep_weights(const float* __restrict__ tw0, const float* __restrict__ bw1,
                             const float* __restrict__ bw2, const float* __restrict__ tw1,
                             const float* __restrict__ tw2, const float* __restrict__ tw3,
                             const float* __restrict__ tw4) {
    int i = blockIdx.x * blockDim.x + threadIdx.x;
    if (i >= SZ_ALL) return;
    if (i < SZ_W0) {
        int n = i >> 9, k = i & 511;
        g_w0[i] = (k < 479) ? __float2bfloat16_rn(tw0[n * 479 + k]) : __float2bfloat16_rn(0.0f);
        return;
    }
    i -= SZ_W0;
    if (i < SZ_BW1) { g_bw1[i] = __float2bfloat16_rn(bw1[i]); return; }
    i -= SZ_BW1;
    if (i < SZ_BW2) { g_bw2[i] = __float2bfloat16_rn(bw2[i]); return; }
    i -= SZ_BW2;
    if (i < SZ_W1)  { g_w1[i] = __float2bfloat16_rn(tw1[i]); return; }
    i -= SZ_W1;
    if (i < SZ_W2)  { g_w2[i] = __float2bfloat16_rn(tw2[i]); return; }
    i -= SZ_W2;
    if (i < SZ_W3)  { g_w3[i] = __float2bfloat16_rn(tw3[i]); return; }
    i -= SZ_W3;
    g_w4[i] = __float2bfloat16_rn(tw4[i]);
}

// ---------------- zero d_out ----------------
__global__ void zero_out(float* __restrict__ o) {
    o[blockIdx.x * blockDim.x + threadIdx.x] = 0.0f;
}
// ---------------- final sigmoid ----------------
__global__ void sigmoid_out(float* __restrict__ o, const float* __restrict__ bias) {
    int i = blockIdx.x * blockDim.x + threadIdx.x;
    o[i] = 1.0f / (1.0f + expf(-(o[i] + bias[0])));
}

// ---------------- bottom MLP layer 0: 16 samples per block ----------------
#define B0S 16
__global__ __launch_bounds__(512)
void bot0_kernel(const float* __restrict__ x,
                 const float* __restrict__ W,
                 const float* __restrict__ bias,
                 bf16* __restrict__ out) {
    const int b0 = blockIdx.x * B0S;
    __shared__ float Ws[512 * 13];
    __shared__ float xs[B0S][13];
    const int tid = threadIdx.x;

    for (int i = tid; i < 512 * 13; i += 512) Ws[i] = W[i];
    if (tid < B0S * 13) xs[tid / 13][tid % 13] = x[(b0 + tid / 13) * 13 + tid % 13];
    __syncthreads();

    float w[13];
#pragma unroll
    for (int k = 0; k < 13; k++) w[k] = Ws[tid * 13 + k];
    const float bv = bias[tid];
#pragma unroll
    for (int s = 0; s < B0S; s++) {
        float acc = bv;
#pragma unroll
        for (int k = 0; k < 13; k++) acc = fmaf(xs[s][k], w[k], acc);
        out[(size_t)(b0 + s) * 512 + tid] = __float2bfloat16_rn(fmaxf(acc, 0.0f));
    }
}

// ---------------- fused gather + tensor-core interaction ----------------
__global__ __launch_bounds__(256)
void interact_kernel(const bf16* __restrict__ x128,
                     const float* __restrict__ emb,
                     const int* __restrict__ lS_i,
                     bf16* __restrict__ z) {
    const int b = blockIdx.x;
    __shared__ __align__(1024) bf16 T[32 * 128];   // 8KB
    const int tid = threadIdx.x, lane = tid & 31, wid = tid >> 5;
    char* Tb = reinterpret_cast<char*>(T);
    bf16* zb = &z[(size_t)b * ZDIM];

    // zero rows 27..31 (5 rows x 256B = 160 x 8B)
    if (tid < 160)
        *reinterpret_cast<uint64_t*>(Tb + (27 + tid / 32) * 256 + (tid % 32) * 8) = 0ull;

    // row 0 = x (bf16, 16 x 16B units; r=0 -> swizzle identity)
    if (tid >= 160 && tid < 176) {
        const int u = tid - 160;
        uint4 v = *reinterpret_cast<const uint4*>(x128 + (size_t)b * 128 + u * 8);
        *reinterpret_cast<uint4*>(Tb + (u << 4)) = v;
    }

    // z[0:128] = x  (64 x 4B), pad zero cols 479..511
    if (tid < 64)
        reinterpret_cast<uint32_t*>(zb)[tid] =
            reinterpret_cast<const uint32_t*>(x128 + (size_t)b * 128)[tid];
    if (tid >= 64 && tid < 97) zb[479 + (tid - 64)] = __float2bfloat16_rn(0.0f);

    // gather rows 1..26 (fp32 -> bf16), 832 float4 tasks
    for (int idx = tid; idx < 26 * 32; idx += 256) {
        const int t = idx >> 5, c = idx & 31;
        const int ix = lS_i[t * BATCH + b];
        const float4 v = *reinterpret_cast<const float4*>(
            &emb[((size_t)t * NROWSZ + ix) * EMBD + c * 4]);
        const int r = t + 1, k = c * 4;
        uint2 pk;
        pk.x = pack_bf16x2(v.x, v.y);
        pk.y = pack_bf16x2(v.z, v.w);
        *reinterpret_cast<uint2*>(
            Tb + r * 256 + ((((k >> 3) ^ (r & 7)) << 4)) + (k & 7) * 2) = pk;
    }
    __syncthreads();

    // Z = T @ T^T ; warp wid: m-half mh = wid&1, n-tile nq = wid>>1
    const uint32_t smb = smem_u32(T);
    const int mh = wid & 1, nq = wid >> 1;
    const int raRow = mh * 16 + (lane & 15);
    const uint32_t aBase = smb + raRow * 256;
    const int rxa = raRow & 7;
    const int uaH = lane >> 4;
    const int rbRow = nq * 8 + (lane & 7);
    const uint32_t bBase = smb + rbRow * 256;
    const int rxb = rbRow & 7;
    const int ubH = (lane >> 3) & 1;

    float acc[4] = {0.f, 0.f, 0.f, 0.f};
#pragma unroll
    for (int ks = 0; ks < 8; ks++) {
        uint32_t a0, a1, a2, a3, b0, b1;
        LDSM4(a0, a1, a2, a3, aBase + (((ks * 2 + uaH) ^ rxa) << 4));
        LDSM2(b0, b1,         bBase + (((ks * 2 + ubH) ^ rxb) << 4));
        HMMA16(acc, a0, a1, a2, a3, b0, b1);
    }

    // scatter lower-tri
    const int row0 = mh * 16 + (lane >> 2);
    const int col0 = nq * 8 + (lane & 3) * 2;
#pragma unroll
    for (int v = 0; v < 4; v++) {
        const int i = row0 + (v >> 1) * 8;
        const int j = col0 + (v & 1);
        if (i < 27 && j < i)
            zb[128 + (i * (i - 1)) / 2 + j] = __float2bfloat16_rn(acc[v]);
    }
}

// ---------------- launch ----------------
static const int SMEM_TM1 = NSTG * (1 * 8192 + 16384);   // 73728

extern "C" void kernel_launch(void* const* d_in, const int* in_sizes, int n_in,
                              void* d_out, int out_size) {
    const float* dense_x = (const float*)d_in[0];
    const int*   lS_i    = (const int*)  d_in[2];
    const float* emb     = (const float*)d_in[3];
    const float* bw0 = (const float*)d_in[4];
    const float* bb0 = (const float*)d_in[5];
    const float* bw1 = (const float*)d_in[6];
    const float* bb1 = (const float*)d_in[7];
    const float* bw2 = (const float*)d_in[8];
    const float* bb2 = (const float*)d_in[9];
    const float* tw0 = (const float*)d_in[10];
    const float* tb0 = (const float*)d_in[11];
    const float* tw1 = (const float*)d_in[12];
    const float* tb1 = (const float*)d_in[13];
    const float* tw2 = (const float*)d_in[14];
    const float* tb2 = (const float*)d_in[15];
    const float* tw3 = (const float*)d_in[16];
    const float* tb3 = (const float*)d_in[17];
    const float* tw4 = (const float*)d_in[18];
    const float* tb4 = (const float*)d_in[19];

    static bf16 *p_x512 = nullptr, *p_x256, *p_x128, *p_z, *p_h1, *p_h2, *p_h3;
    static bf16 *p_bw1, *p_bw2, *p_w0, *p_w1, *p_w2, *p_w3, *p_w4;
    if (!p_x512) {
        cudaGetSymbolAddress((void**)&p_x512, g_x512);
        cudaGetSymbolAddress((void**)&p_x256, g_x256);
        cudaGetSymbolAddress((void**)&p_x128, g_x128);
        cudaGetSymbolAddress((void**)&p_z,    g_z);
        cudaGetSymbolAddress((void**)&p_h1,   g_h1);
        cudaGetSymbolAddress((void**)&p_h2,   g_h2);
        cudaGetSymbolAddress((void**)&p_h3,   g_h3);
        cudaGetSymbolAddress((void**)&p_bw1,  g_bw1);
        cudaGetSymbolAddress((void**)&p_bw2,  g_bw2);
        cudaGetSymbolAddress((void**)&p_w0,   g_w0);
        cudaGetSymbolAddress((void**)&p_w1,   g_w1);
        cudaGetSymbolAddress((void**)&p_w2,   g_w2);
        cudaGetSymbolAddress((void**)&p_w3,   g_w3);
        cudaGetSymbolAddress((void**)&p_w4,   g_w4);
        cudaFuncSetAttribute((const void*)gemm_bf16<512, 1, false>,
                             cudaFuncAttributeMaxDynamicSharedMemorySize, SMEM_TM1);
        cudaFuncSetAttribute((const void*)gemm_bf16<256, 1, false>,
                             cudaFuncAttributeMaxDynamicSharedMemorySize, SMEM_TM1);
        cudaFuncSetAttribute((const void*)gemm_bf16<1024, 1, false>,
                             cudaFuncAttributeMaxDynamicSharedMemorySize, SMEM_TM1);
        cudaFuncSetAttribute((const void*)gemm_bf16<512, 1, true>,
                             cudaFuncAttributeMaxDynamicSharedMemorySize, SMEM_TM1);
    }

    float* outf = (float*)d_out;

    // 1: fused weight prep ; 2: zero output accumulator
    prep_weights<<<(SZ_ALL + 255) / 256, 256>>>(tw0, bw1, bw2, tw1, tw2, tw3, tw4);
    zero_out<<<BATCH / 256, 256>>>(outf);

    // 3: bottom MLP layer 0
    bot0_kernel<<<BATCH / B0S, 512>>>(dense_x, bw0, bb0, p_x512);
    // 4,5: bottom GEMMs
    gemm_bf16<512, 1, false><<<dim3(2, 256), 256, SMEM_TM1>>>(p_x512, p_bw1, bb1, p_x256, 256, nullptr, nullptr);
    gemm_bf16<256, 1, false><<<dim3(1, 256), 256, SMEM_TM1>>>(p_x256, p_bw2, bb2, p_x128, 128, nullptr, nullptr);

    // 6: gather + tensor-core interaction -> z[B,512] bf16
    interact_kernel<<<BATCH, 256>>>(p_x128, emb, lS_i, p_z);

    // 7..9: top MLP (all TM=1: measured 394 TF/s vs TM=2 347)
    gemm_bf16<512, 1, false> <<<dim3(8, 256), 256, SMEM_TM1>>>(p_z,  p_w0, tb0, p_h1, 1024, nullptr, nullptr);
    gemm_bf16<1024, 1, false><<<dim3(8, 256), 256, SMEM_TM1>>>(p_h1, p_w1, tb1, p_h2, 1024, nullptr, nullptr);
    gemm_bf16<1024, 1, false><<<dim3(4, 256), 256, SMEM_TM1>>>(p_h2, p_w2, tb2, p_h3, 512, nullptr, nullptr);

    // 10: top3 GEMM fused with final dot (atomicAdd into outf)
    gemm_bf16<512, 1, true><<<dim3(2, 256), 256, SMEM_TM1>>>(p_h3, p_w3, tb3, nullptr, 256, outf, p_w4);

    // 11: sigmoid
    sigmoid_out<<<BATCH / 256, 256>>>(outf, tb4);
}

// round 15
// speedup vs baseline: 1.1370x; 1.1370x over previous
#include <cuda_runtime.h>
#include <cuda_bf16.h>
#include <math.h>
#include <stdint.h>

#define BATCH 16384
#define NTAB  26
#define NROWSZ 100000
#define EMBD  128
#define ZDIM  512   // 479 padded to 512 (pad columns zeroed)

typedef __nv_bfloat16 bf16;

// ---------------- scratch (device globals: allocation-free) ----------------
__device__ bf16 g_x512[BATCH * 512];
__device__ bf16 g_x256[BATCH * 256];
__device__ bf16 g_x128[BATCH * 128];
__device__ bf16 g_z   [BATCH * ZDIM];
__device__ bf16 g_h1  [BATCH * 1024];
__device__ bf16 g_h2  [BATCH * 1024];
__device__ bf16 g_h3  [BATCH * 512];
// bf16 weights
__device__ bf16 g_bw1 [256 * 512];
__device__ bf16 g_bw2 [128 * 256];
__device__ bf16 g_w0  [1024 * ZDIM];   // tw0 padded 479 -> 512
__device__ bf16 g_w1  [1024 * 1024];
__device__ bf16 g_w2  [512 * 1024];
__device__ bf16 g_w3  [256 * 512];
__device__ bf16 g_w4  [256];

// ======================= PTX helpers =======================
__device__ __forceinline__ uint32_t smem_u32(const void* p) {
    uint32_t a;
    asm("{ .reg .u64 t; cvta.to.shared.u64 t, %1; cvt.u32.u64 %0, t; }" : "=r"(a) : "l"(p));
    return a;
}
__device__ __forceinline__ void cpa16(uint32_t dst, const void* src) {
    asm volatile("cp.async.cg.shared.global [%0], [%1], 16;" :: "r"(dst), "l"(src) : "memory");
}
__device__ __forceinline__ void cpa_commit() {
    asm volatile("cp.async.commit_group;" ::: "memory");
}
template <int N>
__device__ __forceinline__ void cpa_wait() {
    asm volatile("cp.async.wait_group %0;" :: "n"(N) : "memory");
}
__device__ __forceinline__ uint32_t pack_bf16x2(float lo, float hi) {
    uint32_t r;
    asm("cvt.rn.bf16x2.f32 %0, %1, %2;" : "=r"(r) : "f"(hi), "f"(lo));
    return r;
}
#define LDSM4(r0, r1, r2, r3, addr)                                            \
    asm volatile("ldmatrix.sync.aligned.m8n8.x4.shared.b16 {%0,%1,%2,%3}, [%4];" \
                 : "=r"(r0), "=r"(r1), "=r"(r2), "=r"(r3) : "r"(addr))
#define LDSM2(r0, r1, addr)                                                    \
    asm volatile("ldmatrix.sync.aligned.m8n8.x2.shared.b16 {%0,%1}, [%2];"     \
                 : "=r"(r0), "=r"(r1) : "r"(addr))
#define HMMA16(d, a0, a1, a2, a3, b0, b1)                                      \
    asm volatile(                                                              \
        "mma.sync.aligned.m16n8k16.row.col.f32.bf16.bf16.f32 "                 \
        "{%0,%1,%2,%3}, {%4,%5,%6,%7}, {%8,%9}, {%0,%1,%2,%3};"                \
        : "+f"((d)[0]), "+f"((d)[1]), "+f"((d)[2]), "+f"((d)[3])               \
        : "r"(a0), "r"(a1), "r"(a2), "r"(a3), "r"(b0), "r"(b1))

// ======================= bf16 mma.sync GEMM =======================
// C(bf16) = relu(A[M,K] @ W[N,K]^T + bias(fp32)), fp32 accumulate.
// Block (TM*64)x128, 8 warps (4M x 2N), warp tile (TM*16)x64 via m16n8k16.
// K-chunk = 64 bf16 = 128B rows, XOR swizzle u^(r&7).
// TM=2 NSTG=3 (96KB): big layers — B-reuse bound (R14: TM=1 doubles L2 B
// traffic, +45us). TM=1 NSTG=4 (96KB): small-grid layers — occupancy bound.
// FUSE: epilogue computes partial dot with w4 -> atomicAdd(outv) (top3+top4).

template <int K, int TM, bool FUSE>
__global__ __launch_bounds__(256, 2)
void gemm_bf16(const bf16* __restrict__ A, const bf16* __restrict__ W,
               const float* __restrict__ bias, bf16* __restrict__ C,
               int N, float* __restrict__ outv, const bf16* __restrict__ w4v) {
    constexpr int S = (TM == 1) ? 4 : 3;       // pipeline stages
    constexpr int A_BYTES = TM * 8192;         // A stage bytes
    constexpr int STG = A_BYTES + 16384;       // stage total
    extern __shared__ char smraw[];
    const uint32_t smb = smem_u32(smraw);

    const int tid  = threadIdx.x;
    const int lane = tid & 31;
    const int warp = tid >> 5;
    const int bm = blockIdx.y * (TM * 64);
    const int bn = blockIdx.x * 128;
    const int wm = (warp & 3) * (TM * 16);
    const int wn = (warp >> 2) * 64;

    float acc[TM][8][4];
#pragma unroll
    for (int t = 0; t < TM; t++)
#pragma unroll
        for (int u = 0; u < 8; u++)
#pragma unroll
            for (int v = 0; v < 4; v++) acc[t][u][v] = 0.0f;

    // ldmatrix per-warp address constants
    int ra[TM], rxa[TM];
#pragma unroll
    for (int t = 0; t < TM; t++) {
        int row = wm + t * 16 + ((lane >> 3) & 1) * 8 + (lane & 7);
        ra[t]  = row * 128;
        rxa[t] = (row & 7) << 4;
    }
    const int ua = lane >> 4;
    int rb[4], rxb[4];
#pragma unroll
    for (int g = 0; g < 4; g++) {
        int row = wn + g * 16 + ((lane >> 4) & 1) * 8 + (lane & 7);
        rb[g]  = row * 128;
        rxb[g] = (row & 7) << 4;
    }
    const int ub = (lane >> 3) & 1;

    constexpr int NC = K >> 6;                  // >= 4 for all layers
    static_assert(NC >= S - 1, "pipeline deeper than K chunks");

    // loader bases (thread-fixed); slices at constant strides.
    // 8 threads (u0=0..7) cover one full 128B row per cp.async -> coalesced.
    const int r0 = tid >> 3, u0 = tid & 7;
    const bf16* aP = A + (size_t)(bm + r0) * K + u0 * 8;
    const bf16* wP = W + (size_t)(bn + r0) * K + u0 * 8;
    const uint32_t dOff = smb + (uint32_t)(r0 * 128) + (uint32_t)(((u0 ^ (r0 & 7)) << 4));

    auto issue = [&](uint32_t so, const bf16* a, const bf16* w) {
#pragma unroll
        for (int i = 0; i < 2 * TM; i++) cpa16(dOff + so + i * 4096, a + i * (32 * K));
#pragma unroll
        for (int i = 0; i < 4; i++) cpa16(dOff + so + (uint32_t)A_BYTES + i * 4096, w + i * (32 * K));
        cpa_commit();
    };

    // prologue: fill S-1 stages
#pragma unroll
    for (int i = 0; i < S - 1; i++) issue(i * STG, aP + 64 * i, wP + 64 * i);
    const bf16* aN = aP + 64 * (S - 1);
    const bf16* wN = wP + 64 * (S - 1);
    uint32_t soN = (uint32_t)(S - 1) * STG;    // == ((S-1)%S)*STG
    uint32_t soC = 0;

    uint32_t afr[2][TM][4];
    uint32_t bfr[2][4][4];

#pragma unroll 1
    for (int c = 0; c < NC; c++) {
        cpa_wait<S - 2>();
        __syncthreads();

        const uint32_t Ab = smb + soC;
        const uint32_t Bb = Ab + (uint32_t)A_BYTES;
        soC += STG; if (soC == S * STG) soC = 0;

        // prefetch ks=0 fragments FIRST (critical path), then prefetch gmem
#pragma unroll
        for (int t = 0; t < TM; t++)
            LDSM4(afr[0][t][0], afr[0][t][1], afr[0][t][2], afr[0][t][3],
                  Ab + ra[t] + (((ua) << 4) ^ rxa[t]));
#pragma unroll
        for (int g = 0; g < 4; g++)
            LDSM4(bfr[0][g][0], bfr[0][g][1], bfr[0][g][2], bfr[0][g][3],
                  Bb + rb[g] + (((ub) << 4) ^ rxb[g]));

        if (c + S - 1 < NC) {
            issue(soN, aN, wN);
            aN += 64; wN += 64;
            soN += STG; if (soN == S * STG) soN = 0;
        } else {
            cpa_commit();
        }

#pragma unroll
        for (int ks = 0; ks < 4; ks++) {
            const int cur = ks & 1, nxt = cur ^ 1;
            if (ks < 3) {
#pragma unroll
                for (int t = 0; t < TM; t++)
                    LDSM4(afr[nxt][t][0], afr[nxt][t][1], afr[nxt][t][2], afr[nxt][t][3],
                          Ab + ra[t] + ((((ks + 1) * 2 + ua) << 4) ^ rxa[t]));
#pragma unroll
                for (int g = 0; g < 4; g++)
                    LDSM4(bfr[nxt][g][0], bfr[nxt][g][1], bfr[nxt][g][2], bfr[nxt][g][3],
                          Bb + rb[g] + ((((ks + 1) * 2 + ub) << 4) ^ rxb[g]));
            }
#pragma unroll
            for (int g = 0; g < 4; g++)
#pragma unroll
                for (int t = 0; t < TM; t++) {
                    HMMA16(acc[t][2 * g],
                           afr[cur][t][0], afr[cur][t][1], afr[cur][t][2], afr[cur][t][3],
                           bfr[cur][g][0], bfr[cur][g][1]);
                    HMMA16(acc[t][2 * g + 1],
                           afr[cur][t][0], afr[cur][t][1], afr[cur][t][2], afr[cur][t][3],
                           bfr[cur][g][2], bfr[cur][g][3]);
                }
        }
    }

    if constexpr (FUSE) {
        // fused final dot: p[row] += sum_col relu(acc+bias)*w4[col]; TM==1
        float p0 = 0.0f, p1 = 0.0f;
#pragma unroll
        for (int u = 0; u < 8; u++) {
            const int col = bn + wn + u * 8 + (lane & 3) * 2;
            const float b0v = bias[col], b1v = bias[col + 1];
            const float w0 = __bfloat162float(w4v[col]);
            const float w1 = __bfloat162float(w4v[col + 1]);
            p0 = fmaf(fmaxf(acc[0][u][0] + b0v, 0.0f), w0, p0);
            p0 = fmaf(fmaxf(acc[0][u][1] + b1v, 0.0f), w1, p0);
            p1 = fmaf(fmaxf(acc[0][u][2] + b0v, 0.0f), w0, p1);
            p1 = fmaf(fmaxf(acc[0][u][3] + b1v, 0.0f), w1, p1);
        }
        p0 += __shfl_xor_sync(0xffffffffu, p0, 1);
        p0 += __shfl_xor_sync(0xffffffffu, p0, 2);
        p1 += __shfl_xor_sync(0xffffffffu, p1, 1);
        p1 += __shfl_xor_sync(0xffffffffu, p1, 2);
        if ((lane & 3) == 0) {
            const int row = bm + wm + (lane >> 2);
            atomicAdd(&outv[row], p0);
            atomicAdd(&outv[row + 8], p1);
        }
    } else {
        // epilogue: bias + relu -> bf16
#pragma unroll
        for (int t = 0; t < TM; t++) {
            const int row = bm + wm + t * 16 + (lane >> 2);
#pragma unroll
            for (int u = 0; u < 8; u++) {
                const int col = bn + wn + u * 8 + (lane & 3) * 2;
                const float b0v = bias[col], b1v = bias[col + 1];
                uint32_t o0 = pack_bf16x2(fmaxf(acc[t][u][0] + b0v, 0.0f),
                                          fmaxf(acc[t][u][1] + b1v, 0.0f));
                uint32_t o1 = pack_bf16x2(fmaxf(acc[t][u][2] + b0v, 0.0f),
                                          fmaxf(acc[t][u][3] + b1v, 0.0f));
                *reinterpret_cast<uint32_t*>(&C[(size_t)row * N + col]) = o0;
                *reinterpret_cast<uint32_t*>(&C[(size_t)(row + 8) * N + col]) = o1;
            }
        }
    }
}

// ---------------- fused weight prep (ONE launch) ----------------
#define SZ_W0  (1024 * ZDIM)
#define SZ_BW1 (256 * 512)
#define SZ_BW2 (128 * 256)
#define SZ_W1  (1024 * 1024)
#define SZ_W2  (512 * 1024)
#define SZ_W3  (256 * 512)
#define SZ_W4  (256)
#define SZ_ALL (SZ_W0 + SZ_BW1 + SZ_BW2 + SZ_W1 + SZ_W2 + SZ_W3 + SZ_W4)

__global__ void prep_weights(const float* __restrict__ tw0, const float* __restrict__ bw1,
                             const float* __restrict__ bw2, const float* __restrict__ tw1,
                             const float* __restrict__ tw2, const float* __restrict__ tw3,
                             const float* __restrict__ tw4) {
    int i = blockIdx.x * blockDim.x + threadIdx.x;
    if (i >= SZ_ALL) return;
    if (i < SZ_W0) {
        int n = i >> 9, k = i & 511;
        g_w0[i] = (k < 479) ? __float2bfloat16_rn(tw0[n * 479 + k]) : __float2bfloat16_rn(0.0f);
        return;
    }
    i -= SZ_W0;
    if (i < SZ_BW1) { g_bw1[i] = __float2bfloat16_rn(bw1[i]); return; }
    i -= SZ_BW1;
    if (i < SZ_BW2) { g_bw2[i] = __float2bfloat16_rn(bw2[i]); return; }
    i -= SZ_BW2;
    if (i < SZ_W1)  { g_w1[i] = __float2bfloat16_rn(tw1[i]); return; }
    i -= SZ_W1;
    if (i < SZ_W2)  { g_w2[i] = __float2bfloat16_rn(tw2[i]); return; }
    i -= SZ_W2;
    if (i < SZ_W3)  { g_w3[i] = __float2bfloat16_rn(tw3[i]); return; }
    i -= SZ_W3;
    g_w4[i] = __float2bfloat16_rn(tw4[i]);
}

// ---------------- zero d_out ----------------
__global__ void zero_out(float* __restrict__ o) {
    o[blockIdx.x * blockDim.x + threadIdx.x] = 0.0f;
}
// ---------------- final sigmoid ----------------
__global__ void sigmoid_out(float* __restrict__ o, const float* __restrict__ bias) {
    int i = blockIdx.x * blockDim.x + threadIdx.x;
    o[i] = 1.0f / (1.0f + expf(-(o[i] + bias[0])));
}

// ---------------- bottom MLP layer 0: 16 samples per block ----------------
#define B0S 16
__global__ __launch_bounds__(512)
void bot0_kernel(const float* __restrict__ x,
                 const float* __restrict__ W,
                 const float* __restrict__ bias,
                 bf16* __restrict__ out) {
    const int b0 = blockIdx.x * B0S;
    __shared__ float Ws[512 * 13];
    __shared__ float xs[B0S][13];
    const int tid = threadIdx.x;

    for (int i = tid; i < 512 * 13; i += 512) Ws[i] = W[i];
    if (tid < B0S * 13) xs[tid / 13][tid % 13] = x[(b0 + tid / 13) * 13 + tid % 13];
    __syncthreads();

    float w[13];
#pragma unroll
    for (int k = 0; k < 13; k++) w[k] = Ws[tid * 13 + k];
    const float bv = bias[tid];
#pragma unroll
    for (int s = 0; s < B0S; s++) {
        float acc = bv;
#pragma unroll
        for (int k = 0; k < 13; k++) acc = fmaf(xs[s][k], w[k], acc);
        out[(size_t)(b0 + s) * 512 + tid] = __float2bfloat16_rn(fmaxf(acc, 0.0f));
    }
}

// ---------------- fused gather + tensor-core interaction ----------------
__global__ __launch_bounds__(256)
void interact_kernel(const bf16* __restrict__ x128,
                     const float* __restrict__ emb,
                     const int* __restrict__ lS_i,
                     bf16* __restrict__ z) {
    const int b = blockIdx.x;
    __shared__ __align__(1024) bf16 T[32 * 128];   // 8KB
    const int tid = threadIdx.x, lane = tid & 31, wid = tid >> 5;
    char* Tb = reinterpret_cast<char*>(T);
    bf16* zb = &z[(size_t)b * ZDIM];

    // zero rows 27..31 (5 rows x 256B = 160 x 8B)
    if (tid < 160)
        *reinterpret_cast<uint64_t*>(Tb + (27 + tid / 32) * 256 + (tid % 32) * 8) = 0ull;

    // row 0 = x (bf16, 16 x 16B units; r=0 -> swizzle identity)
    if (tid >= 160 && tid < 176) {
        const int u = tid - 160;
        uint4 v = *reinterpret_cast<const uint4*>(x128 + (size_t)b * 128 + u * 8);
        *reinterpret_cast<uint4*>(Tb + (u << 4)) = v;
    }

    // z[0:128] = x  (64 x 4B), pad zero cols 479..511
    if (tid < 64)
        reinterpret_cast<uint32_t*>(zb)[tid] =
            reinterpret_cast<const uint32_t*>(x128 + (size_t)b * 128)[tid];
    if (tid >= 64 && tid < 97) zb[479 + (tid - 64)] = __float2bfloat16_rn(0.0f);

    // gather rows 1..26 (fp32 -> bf16), 832 float4 tasks
    for (int idx = tid; idx < 26 * 32; idx += 256) {
        const int t = idx >> 5, c = idx & 31;
        const int ix = lS_i[t * BATCH + b];
        const float4 v = *reinterpret_cast<const float4*>(
            &emb[((size_t)t * NROWSZ + ix) * EMBD + c * 4]);
        const int r = t + 1, k = c * 4;
        uint2 pk;
        pk.x = pack_bf16x2(v.x, v.y);
        pk.y = pack_bf16x2(v.z, v.w);
        *reinterpret_cast<uint2*>(
            Tb + r * 256 + ((((k >> 3) ^ (r & 7)) << 4)) + (k & 7) * 2) = pk;
    }
    __syncthreads();

    // Z = T @ T^T ; warp wid: m-half mh = wid&1, n-tile nq = wid>>1
    const uint32_t smb = smem_u32(T);
    const int mh = wid & 1, nq = wid >> 1;
    const int raRow = mh * 16 + (lane & 15);
    const uint32_t aBase = smb + raRow * 256;
    const int rxa = raRow & 7;
    const int uaH = lane >> 4;
    const int rbRow = nq * 8 + (lane & 7);
    const uint32_t bBase = smb + rbRow * 256;
    const int rxb = rbRow & 7;
    const int ubH = (lane >> 3) & 1;

    float acc[4] = {0.f, 0.f, 0.f, 0.f};
#pragma unroll
    for (int ks = 0; ks < 8; ks++) {
        uint32_t a0, a1, a2, a3, b0, b1;
        LDSM4(a0, a1, a2, a3, aBase + (((ks * 2 + uaH) ^ rxa) << 4));
        LDSM2(b0, b1,         bBase + (((ks * 2 + ubH) ^ rxb) << 4));
        HMMA16(acc, a0, a1, a2, a3, b0, b1);
    }

    // scatter lower-tri
    const int row0 = mh * 16 + (lane >> 2);
    const int col0 = nq * 8 + (lane & 3) * 2;
#pragma unroll
    for (int v = 0; v < 4; v++) {
        const int i = row0 + (v >> 1) * 8;
        const int j = col0 + (v & 1);
        if (i < 27 && j < i)
            zb[128 + (i * (i - 1)) / 2 + j] = __float2bfloat16_rn(acc[v]);
    }
}

// ---------------- launch ----------------
static const int SMEM_TM1 = 4 * (1 * 8192 + 16384);   // 98304 (NSTG=4)
static const int SMEM_TM2 = 3 * (2 * 8192 + 16384);   // 98304 (NSTG=3)

extern "C" void kernel_launch(void* const* d_in, const int* in_sizes, int n_in,
                              void* d_out, int out_size) {
    const float* dense_x = (const float*)d_in[0];
    const int*   lS_i    = (const int*)  d_in[2];
    const float* emb     = (const float*)d_in[3];
    const float* bw0 = (const float*)d_in[4];
    const float* bb0 = (const float*)d_in[5];
    const float* bw1 = (const float*)d_in[6];
    const float* bb1 = (const float*)d_in[7];
    const float* bw2 = (const float*)d_in[8];
    const float* bb2 = (const float*)d_in[9];
    const float* tw0 = (const float*)d_in[10];
    const float* tb0 = (const float*)d_in[11];
    const float* tw1 = (const float*)d_in[12];
    const float* tb1 = (const float*)d_in[13];
    const float* tw2 = (const float*)d_in[14];
    const float* tb2 = (const float*)d_in[15];
    const float* tw3 = (const float*)d_in[16];
    const float* tb3 = (const float*)d_in[17];
    const float* tw4 = (const float*)d_in[18];
    const float* tb4 = (const float*)d_in[19];

    static bf16 *p_x512 = nullptr, *p_x256, *p_x128, *p_z, *p_h1, *p_h2, *p_h3;
    static bf16 *p_bw1, *p_bw2, *p_w0, *p_w1, *p_w2, *p_w3, *p_w4;
    if (!p_x512) {
        cudaGetSymbolAddress((void**)&p_x512, g_x512);
        cudaGetSymbolAddress((void**)&p_x256, g_x256);
        cudaGetSymbolAddress((void**)&p_x128, g_x128);
        cudaGetSymbolAddress((void**)&p_z,    g_z);
        cudaGetSymbolAddress((void**)&p_h1,   g_h1);
        cudaGetSymbolAddress((void**)&p_h2,   g_h2);
        cudaGetSymbolAddress((void**)&p_h3,   g_h3);
        cudaGetSymbolAddress((void**)&p_bw1,  g_bw1);
        cudaGetSymbolAddress((void**)&p_bw2,  g_bw2);
        cudaGetSymbolAddress((void**)&p_w0,   g_w0);
        cudaGetSymbolAddress((void**)&p_w1,   g_w1);
        cudaGetSymbolAddress((void**)&p_w2,   g_w2);
        cudaGetSymbolAddress((void**)&p_w3,   g_w3);
        cudaGetSymbolAddress((void**)&p_w4,   g_w4);
        cudaFuncSetAttribute((const void*)gemm_bf16<512, 1, false>,
                             cudaFuncAttributeMaxDynamicSharedMemorySize, SMEM_TM1);
        cudaFuncSetAttribute((const void*)gemm_bf16<256, 1, false>,
                             cudaFuncAttributeMaxDynamicSharedMemorySize, SMEM_TM1);
        cudaFuncSetAttribute((const void*)gemm_bf16<512, 1, true>,
                             cudaFuncAttributeMaxDynamicSharedMemorySize, SMEM_TM1);
        cudaFuncSetAttribute((const void*)gemm_bf16<512, 2, false>,
                             cudaFuncAttributeMaxDynamicSharedMemorySize, SMEM_TM2);
        cudaFuncSetAttribute((const void*)gemm_bf16<1024, 2, false>,
                             cudaFuncAttributeMaxDynamicSharedMemorySize, SMEM_TM2);
    }

    float* outf = (float*)d_out;

    // 1: fused weight prep ; 2: zero output accumulator
    prep_weights<<<(SZ_ALL + 255) / 256, 256>>>(tw0, bw1, bw2, tw1, tw2, tw3, tw4);
    zero_out<<<BATCH / 256, 256>>>(outf);

    // 3: bottom MLP layer 0
    bot0_kernel<<<BATCH / B0S, 512>>>(dense_x, bw0, bb0, p_x512);
    // 4,5: bottom GEMMs (TM=1 NSTG=4: occupancy-bound small layers)
    gemm_bf16<512, 1, false><<<dim3(2, 256), 256, SMEM_TM1>>>(p_x512, p_bw1, bb1, p_x256, 256, nullptr, nullptr);
    gemm_bf16<256, 1, false><<<dim3(1, 256), 256, SMEM_TM1>>>(p_x256, p_bw2, bb2, p_x128, 128, nullptr, nullptr);

    // 6: gather + tensor-core interaction -> z[B,512] bf16
    interact_kernel<<<BATCH, 256>>>(p_x128, emb, lS_i, p_z);

    // 7..9: top MLP big layers (TM=2: B-reuse bound, proven 333us config)
    gemm_bf16<512, 2, false> <<<dim3(8, 128), 256, SMEM_TM2>>>(p_z,  p_w0, tb0, p_h1, 1024, nullptr, nullptr);
    gemm_bf16<1024, 2, false><<<dim3(8, 128), 256, SMEM_TM2>>>(p_h1, p_w1, tb1, p_h2, 1024, nullptr, nullptr);
    gemm_bf16<1024, 2, false><<<dim3(4, 128), 256, SMEM_TM2>>>(p_h2, p_w2, tb2, p_h3, 512, nullptr, nullptr);

    // 10: top3 GEMM fused with final dot (atomicAdd into outf)
    gemm_bf16<512, 1, true><<<dim3(2, 256), 256, SMEM_TM1>>>(p_h3, p_w3, tb3, nullptr, 256, outf, p_w4);

    // 11: sigmoid
    sigmoid_out<<<BATCH / 256, 256>>>(outf, tb4);
}

// round 16
// speedup vs baseline: 1.1407x; 1.0032x over previous
#include <cuda_runtime.h>
#include <cuda_bf16.h>
#include <math.h>
#include <stdint.h>

#define BATCH 16384
#define NTAB  26
#define NROWSZ 100000
#define EMBD  128
#define ZDIM  512   // 479 padded to 512 (pad columns zeroed)

typedef __nv_bfloat16 bf16;

// ---------------- scratch (device globals: allocation-free) ----------------
__device__ bf16 g_x512[BATCH * 512];
__device__ bf16 g_x256[BATCH * 256];
__device__ bf16 g_x128[BATCH * 128];
__device__ bf16 g_z   [BATCH * ZDIM];
__device__ bf16 g_h1  [BATCH * 1024];
__device__ bf16 g_h2  [BATCH * 1024];
__device__ bf16 g_h3  [BATCH * 512];
// bf16 weights
__device__ bf16 g_bw1 [256 * 512];
__device__ bf16 g_bw2 [128 * 256];
__device__ bf16 g_w0  [1024 * ZDIM];   // tw0 padded 479 -> 512
__device__ bf16 g_w1  [1024 * 1024];
__device__ bf16 g_w2  [512 * 1024];
__device__ bf16 g_w3  [256 * 512];
__device__ bf16 g_w4  [256];

// ======================= PTX helpers =======================
__device__ __forceinline__ uint32_t smem_u32(const void* p) {
    uint32_t a;
    asm("{ .reg .u64 t; cvta.to.shared.u64 t, %1; cvt.u32.u64 %0, t; }" : "=r"(a) : "l"(p));
    return a;
}
__device__ __forceinline__ void cpa16(uint32_t dst, const void* src) {
    asm volatile("cp.async.cg.shared.global [%0], [%1], 16;" :: "r"(dst), "l"(src) : "memory");
}
__device__ __forceinline__ void cpa_commit() {
    asm volatile("cp.async.commit_group;" ::: "memory");
}
template <int N>
__device__ __forceinline__ void cpa_wait() {
    asm volatile("cp.async.wait_group %0;" :: "n"(N) : "memory");
}
__device__ __forceinline__ uint32_t pack_bf16x2(float lo, float hi) {
    uint32_t r;
    asm("cvt.rn.bf16x2.f32 %0, %1, %2;" : "=r"(r) : "f"(hi), "f"(lo));
    return r;
}
#define LDSM4(r0, r1, r2, r3, addr)                                            \
    asm volatile("ldmatrix.sync.aligned.m8n8.x4.shared.b16 {%0,%1,%2,%3}, [%4];" \
                 : "=r"(r0), "=r"(r1), "=r"(r2), "=r"(r3) : "r"(addr))
#define LDSM2(r0, r1, addr)                                                    \
    asm volatile("ldmatrix.sync.aligned.m8n8.x2.shared.b16 {%0,%1}, [%2];"     \
                 : "=r"(r0), "=r"(r1) : "r"(addr))
#define HMMA16(d, a0, a1, a2, a3, b0, b1)                                      \
    asm volatile(                                                              \
        "mma.sync.aligned.m16n8k16.row.col.f32.bf16.bf16.f32 "                 \
        "{%0,%1,%2,%3}, {%4,%5,%6,%7}, {%8,%9}, {%0,%1,%2,%3};"                \
        : "+f"((d)[0]), "+f"((d)[1]), "+f"((d)[2]), "+f"((d)[3])               \
        : "r"(a0), "r"(a1), "r"(a2), "r"(a3), "r"(b0), "r"(b1))

// ======================= bf16 mma.sync GEMM =======================
// C(bf16) = relu(A[M,K] @ W[N,K]^T + bias(fp32)), fp32 accumulate.
// Block (TM*64)x128, 8 warps (4M x 2N), warp tile (TM*16)x64 via m16n8k16.
// K-chunk = 64 bf16 = 128B rows, XOR swizzle u^(r&7). NSTG=3.
// TM=2, 2 CTAs/SM: big layers (B-reuse bound; R14 showed TM=1 doubles B L2
// traffic). TM=1, 3 CTAs/SM (24 warps/SM): occupancy-bound small-grid layers
// (R10/R15: issue%~22, warps/SM is the dominant variable).
// FUSE: epilogue computes partial dot with w4 -> atomicAdd(outv) (top3+top4).
#define NSTG 3

template <int K, int TM, bool FUSE>
__global__ __launch_bounds__(256, (TM == 1) ? 3 : 2)
void gemm_bf16(const bf16* __restrict__ A, const bf16* __restrict__ W,
               const float* __restrict__ bias, bf16* __restrict__ C,
               int N, float* __restrict__ outv, const bf16* __restrict__ w4v) {
    constexpr int S = NSTG;
    constexpr int A_BYTES = TM * 8192;         // A stage bytes
    constexpr int STG = A_BYTES + 16384;       // stage total
    extern __shared__ char smraw[];
    const uint32_t smb = smem_u32(smraw);

    const int tid  = threadIdx.x;
    const int lane = tid & 31;
    const int warp = tid >> 5;
    const int bm = blockIdx.y * (TM * 64);
    const int bn = blockIdx.x * 128;
    const int wm = (warp & 3) * (TM * 16);
    const int wn = (warp >> 2) * 64;

    float acc[TM][8][4];
#pragma unroll
    for (int t = 0; t < TM; t++)
#pragma unroll
        for (int u = 0; u < 8; u++)
#pragma unroll
            for (int v = 0; v < 4; v++) acc[t][u][v] = 0.0f;

    // ldmatrix per-warp address constants
    int ra[TM], rxa[TM];
#pragma unroll
    for (int t = 0; t < TM; t++) {
        int row = wm + t * 16 + ((lane >> 3) & 1) * 8 + (lane & 7);
        ra[t]  = row * 128;
        rxa[t] = (row & 7) << 4;
    }
    const int ua = lane >> 4;
    int rb[4], rxb[4];
#pragma unroll
    for (int g = 0; g < 4; g++) {
        int row = wn + g * 16 + ((lane >> 4) & 1) * 8 + (lane & 7);
        rb[g]  = row * 128;
        rxb[g] = (row & 7) << 4;
    }
    const int ub = (lane >> 3) & 1;

    constexpr int NC = K >> 6;
    static_assert(NC >= S - 1, "pipeline deeper than K chunks");

    // loader bases (thread-fixed); slices at constant strides.
    // 8 threads (u0=0..7) cover one full 128B row per cp.async -> coalesced.
    const int r0 = tid >> 3, u0 = tid & 7;
    const bf16* aP = A + (size_t)(bm + r0) * K + u0 * 8;
    const bf16* wP = W + (size_t)(bn + r0) * K + u0 * 8;
    const uint32_t dOff = smb + (uint32_t)(r0 * 128) + (uint32_t)(((u0 ^ (r0 & 7)) << 4));

    auto issue = [&](uint32_t so, const bf16* a, const bf16* w) {
#pragma unroll
        for (int i = 0; i < 2 * TM; i++) cpa16(dOff + so + i * 4096, a + i * (32 * K));
#pragma unroll
        for (int i = 0; i < 4; i++) cpa16(dOff + so + (uint32_t)A_BYTES + i * 4096, w + i * (32 * K));
        cpa_commit();
    };

    // prologue: fill S-1 stages
#pragma unroll
    for (int i = 0; i < S - 1; i++) issue(i * STG, aP + 64 * i, wP + 64 * i);
    const bf16* aN = aP + 64 * (S - 1);
    const bf16* wN = wP + 64 * (S - 1);
    uint32_t soN = (uint32_t)(S - 1) * STG;
    uint32_t soC = 0;

    uint32_t afr[2][TM][4];
    uint32_t bfr[2][4][4];

#pragma unroll 1
    for (int c = 0; c < NC; c++) {
        cpa_wait<S - 2>();
        __syncthreads();

        const uint32_t Ab = smb + soC;
        const uint32_t Bb = Ab + (uint32_t)A_BYTES;
        soC += STG; if (soC == S * STG) soC = 0;

        // prefetch ks=0 fragments FIRST (critical path), then prefetch gmem
#pragma unroll
        for (int t = 0; t < TM; t++)
            LDSM4(afr[0][t][0], afr[0][t][1], afr[0][t][2], afr[0][t][3],
                  Ab + ra[t] + (((ua) << 4) ^ rxa[t]));
#pragma unroll
        for (int g = 0; g < 4; g++)
            LDSM4(bfr[0][g][0], bfr[0][g][1], bfr[0][g][2], bfr[0][g][3],
                  Bb + rb[g] + (((ub) << 4) ^ rxb[g]));

        if (c + S - 1 < NC) {
            issue(soN, aN, wN);
            aN += 64; wN += 64;
            soN += STG; if (soN == S * STG) soN = 0;
        } else {
            cpa_commit();
        }

#pragma unroll
        for (int ks = 0; ks < 4; ks++) {
            const int cur = ks & 1, nxt = cur ^ 1;
            if (ks < 3) {
#pragma unroll
                for (int t = 0; t < TM; t++)
                    LDSM4(afr[nxt][t][0], afr[nxt][t][1], afr[nxt][t][2], afr[nxt][t][3],
                          Ab + ra[t] + ((((ks + 1) * 2 + ua) << 4) ^ rxa[t]));
#pragma unroll
                for (int g = 0; g < 4; g++)
                    LDSM4(bfr[nxt][g][0], bfr[nxt][g][1], bfr[nxt][g][2], bfr[nxt][g][3],
                          Bb + rb[g] + ((((ks + 1) * 2 + ub) << 4) ^ rxb[g]));
            }
#pragma unroll
            for (int g = 0; g < 4; g++)
#pragma unroll
                for (int t = 0; t < TM; t++) {
                    HMMA16(acc[t][2 * g],
                           afr[cur][t][0], afr[cur][t][1], afr[cur][t][2], afr[cur][t][3],
                           bfr[cur][g][0], bfr[cur][g][1]);
                    HMMA16(acc[t][2 * g + 1],
                           afr[cur][t][0], afr[cur][t][1], afr[cur][t][2], afr[cur][t][3],
                           bfr[cur][g][2], bfr[cur][g][3]);
                }
        }
    }

    if constexpr (FUSE) {
        // fused final dot: p[row] += sum_col relu(acc+bias)*w4[col]; TM==1
        float p0 = 0.0f, p1 = 0.0f;
#pragma unroll
        for (int u = 0; u < 8; u++) {
            const int col = bn + wn + u * 8 + (lane & 3) * 2;
            const float b0v = bias[col], b1v = bias[col + 1];
            const float w0 = __bfloat162float(w4v[col]);
            const float w1 = __bfloat162float(w4v[col + 1]);
            p0 = fmaf(fmaxf(acc[0][u][0] + b0v, 0.0f), w0, p0);
            p0 = fmaf(fmaxf(acc[0][u][1] + b1v, 0.0f), w1, p0);
            p1 = fmaf(fmaxf(acc[0][u][2] + b0v, 0.0f), w0, p1);
            p1 = fmaf(fmaxf(acc[0][u][3] + b1v, 0.0f), w1, p1);
        }
        p0 += __shfl_xor_sync(0xffffffffu, p0, 1);
        p0 += __shfl_xor_sync(0xffffffffu, p0, 2);
        p1 += __shfl_xor_sync(0xffffffffu, p1, 1);
        p1 += __shfl_xor_sync(0xffffffffu, p1, 2);
        if ((lane & 3) == 0) {
            const int row = bm + wm + (lane >> 2);
            atomicAdd(&outv[row], p0);
            atomicAdd(&outv[row + 8], p1);
        }
    } else {
        // epilogue: bias + relu -> bf16
#pragma unroll
        for (int t = 0; t < TM; t++) {
            const int row = bm + wm + t * 16 + (lane >> 2);
#pragma unroll
            for (int u = 0; u < 8; u++) {
                const int col = bn + wn + u * 8 + (lane & 3) * 2;
                const float b0v = bias[col], b1v = bias[col + 1];
                uint32_t o0 = pack_bf16x2(fmaxf(acc[t][u][0] + b0v, 0.0f),
                                          fmaxf(acc[t][u][1] + b1v, 0.0f));
                uint32_t o1 = pack_bf16x2(fmaxf(acc[t][u][2] + b0v, 0.0f),
                                          fmaxf(acc[t][u][3] + b1v, 0.0f));
                *reinterpret_cast<uint32_t*>(&C[(size_t)row * N + col]) = o0;
                *reinterpret_cast<uint32_t*>(&C[(size_t)(row + 8) * N + col]) = o1;
            }
        }
    }
}

// ---------------- fused weight prep + output zero (ONE launch) ----------------
#define SZ_W0  (1024 * ZDIM)
#define SZ_BW1 (256 * 512)
#define SZ_BW2 (128 * 256)
#define SZ_W1  (1024 * 1024)
#define SZ_W2  (512 * 1024)
#define SZ_W3  (256 * 512)
#define SZ_W4  (256)
#define SZ_ALL (SZ_W0 + SZ_BW1 + SZ_BW2 + SZ_W1 + SZ_W2 + SZ_W3 + SZ_W4 + BATCH)

__global__ void prep_weights(const float* __restrict__ tw0, const float* __restrict__ bw1,
                             const float* __restrict__ bw2, const float* __restrict__ tw1,
                             const float* __restrict__ tw2, const float* __restrict__ tw3,
                             const float* __restrict__ tw4, float* __restrict__ outf) {
    int i = blockIdx.x * blockDim.x + threadIdx.x;
    if (i >= SZ_ALL) return;
    if (i < SZ_W0) {
        int n = i >> 9, k = i & 511;
        g_w0[i] = (k < 479) ? __float2bfloat16_rn(tw0[n * 479 + k]) : __float2bfloat16_rn(0.0f);
        return;
    }
    i -= SZ_W0;
    if (i < SZ_BW1) { g_bw1[i] = __float2bfloat16_rn(bw1[i]); return; }
    i -= SZ_BW1;
    if (i < SZ_BW2) { g_bw2[i] = __float2bfloat16_rn(bw2[i]); return; }
    i -= SZ_BW2;
    if (i < SZ_W1)  { g_w1[i] = __float2bfloat16_rn(tw1[i]); return; }
    i -= SZ_W1;
    if (i < SZ_W2)  { g_w2[i] = __float2bfloat16_rn(tw2[i]); return; }
    i -= SZ_W2;
    if (i < SZ_W3)  { g_w3[i] = __float2bfloat16_rn(tw3[i]); return; }
    i -= SZ_W3;
    if (i < SZ_W4)  { g_w4[i] = __float2bfloat16_rn(tw4[i]); return; }
    i -= SZ_W4;
    outf[i] = 0.0f;
}

// ---------------- final sigmoid ----------------
__global__ void sigmoid_out(float* __restrict__ o, const float* __restrict__ bias) {
    int i = blockIdx.x * blockDim.x + threadIdx.x;
    o[i] = 1.0f / (1.0f + expf(-(o[i] + bias[0])));
}

// ---------------- bottom MLP layer 0: 16 samples per block ----------------
#define B0S 16
__global__ __launch_bounds__(512)
void bot0_kernel(const float* __restrict__ x,
                 const float* __restrict__ W,
                 const float* __restrict__ bias,
                 bf16* __restrict__ out) {
    const int b0 = blockIdx.x * B0S;
    __shared__ float Ws[512 * 13];
    __shared__ float xs[B0S][13];
    const int tid = threadIdx.x;

    for (int i = tid; i < 512 * 13; i += 512) Ws[i] = W[i];
    if (tid < B0S * 13) xs[tid / 13][tid % 13] = x[(b0 + tid / 13) * 13 + tid % 13];
    __syncthreads();

    float w[13];
#pragma unroll
    for (int k = 0; k < 13; k++) w[k] = Ws[tid * 13 + k];
    const float bv = bias[tid];
#pragma unroll
    for (int s = 0; s < B0S; s++) {
        float acc = bv;
#pragma unroll
        for (int k = 0; k < 13; k++) acc = fmaf(xs[s][k], w[k], acc);
        out[(size_t)(b0 + s) * 512 + tid] = __float2bfloat16_rn(fmaxf(acc, 0.0f));
    }
}

// ---------------- fused gather + tensor-core interaction ----------------
__global__ __launch_bounds__(256)
void interact_kernel(const bf16* __restrict__ x128,
                     const float* __restrict__ emb,
                     const int* __restrict__ lS_i,
                     bf16* __restrict__ z) {
    const int b = blockIdx.x;
    __shared__ __align__(1024) bf16 T[32 * 128];   // 8KB
    const int tid = threadIdx.x, lane = tid & 31, wid = tid >> 5;
    char* Tb = reinterpret_cast<char*>(T);
    bf16* zb = &z[(size_t)b * ZDIM];

    // zero rows 27..31 (5 rows x 256B = 160 x 8B)
    if (tid < 160)
        *reinterpret_cast<uint64_t*>(Tb + (27 + tid / 32) * 256 + (tid % 32) * 8) = 0ull;

    // row 0 = x (bf16, 16 x 16B units; r=0 -> swizzle identity)
    if (tid >= 160 && tid < 176) {
        const int u = tid - 160;
        uint4 v = *reinterpret_cast<const uint4*>(x128 + (size_t)b * 128 + u * 8);
        *reinterpret_cast<uint4*>(Tb + (u << 4)) = v;
    }

    // z[0:128] = x  (64 x 4B), pad zero cols 479..511
    if (tid < 64)
        reinterpret_cast<uint32_t*>(zb)[tid] =
            reinterpret_cast<const uint32_t*>(x128 + (size_t)b * 128)[tid];
    if (tid >= 64 && tid < 97) zb[479 + (tid - 64)] = __float2bfloat16_rn(0.0f);

    // gather rows 1..26 (fp32 -> bf16), 832 float4 tasks
    for (int idx = tid; idx < 26 * 32; idx += 256) {
        const int t = idx >> 5, c = idx & 31;
        const int ix = lS_i[t * BATCH + b];
        const float4 v = *reinterpret_cast<const float4*>(
            &emb[((size_t)t * NROWSZ + ix) * EMBD + c * 4]);
        const int r = t + 1, k = c * 4;
        uint2 pk;
        pk.x = pack_bf16x2(v.x, v.y);
        pk.y = pack_bf16x2(v.z, v.w);
        *reinterpret_cast<uint2*>(
            Tb + r * 256 + ((((k >> 3) ^ (r & 7)) << 4)) + (k & 7) * 2) = pk;
    }
    __syncthreads();

    // Z = T @ T^T ; warp wid: m-half mh = wid&1, n-tile nq = wid>>1
    const uint32_t smb = smem_u32(T);
    const int mh = wid & 1, nq = wid >> 1;
    const int raRow = mh * 16 + (lane & 15);
    const uint32_t aBase = smb + raRow * 256;
    const int rxa = raRow & 7;
    const int uaH = lane >> 4;
    const int rbRow = nq * 8 + (lane & 7);
    const uint32_t bBase = smb + rbRow * 256;
    const int rxb = rbRow & 7;
    const int ubH = (lane >> 3) & 1;

    float acc[4] = {0.f, 0.f, 0.f, 0.f};
#pragma unroll
    for (int ks = 0; ks < 8; ks++) {
        uint32_t a0, a1, a2, a3, b0, b1;
        LDSM4(a0, a1, a2, a3, aBase + (((ks * 2 + uaH) ^ rxa) << 4));
        LDSM2(b0, b1,         bBase + (((ks * 2 + ubH) ^ rxb) << 4));
        HMMA16(acc, a0, a1, a2, a3, b0, b1);
    }

    // scatter lower-tri
    const int row0 = mh * 16 + (lane >> 2);
    const int col0 = nq * 8 + (lane & 3) * 2;
#pragma unroll
    for (int v = 0; v < 4; v++) {
        const int i = row0 + (v >> 1) * 8;
        const int j = col0 + (v & 1);
        if (i < 27 && j < i)
            zb[128 + (i * (i - 1)) / 2 + j] = __float2bfloat16_rn(acc[v]);
    }
}

// ---------------- launch ----------------
static const int SMEM_TM1 = NSTG * (1 * 8192 + 16384);   // 73728 (3 CTAs/SM)
static const int SMEM_TM2 = NSTG * (2 * 8192 + 16384);   // 98304 (2 CTAs/SM)

extern "C" void kernel_launch(void* const* d_in, const int* in_sizes, int n_in,
                              void* d_out, int out_size) {
    const float* dense_x = (const float*)d_in[0];
    const int*   lS_i    = (const int*)  d_in[2];
    const float* emb     = (const float*)d_in[3];
    const float* bw0 = (const float*)d_in[4];
    const float* bb0 = (const float*)d_in[5];
    const float* bw1 = (const float*)d_in[6];
    const float* bb1 = (const float*)d_in[7];
    const float* bw2 = (const float*)d_in[8];
    const float* bb2 = (const float*)d_in[9];
    const float* tw0 = (const float*)d_in[10];
    const float* tb0 = (const float*)d_in[11];
    const float* tw1 = (const float*)d_in[12];
    const float* tb1 = (const float*)d_in[13];
    const float* tw2 = (const float*)d_in[14];
    const float* tb2 = (const float*)d_in[15];
    const float* tw3 = (const float*)d_in[16];
    const float* tb3 = (const float*)d_in[17];
    const float* tw4 = (const float*)d_in[18];
    const float* tb4 = (const float*)d_in[19];

    static bf16 *p_x512 = nullptr, *p_x256, *p_x128, *p_z, *p_h1, *p_h2, *p_h3;
    static bf16 *p_bw1, *p_bw2, *p_w0, *p_w1, *p_w2, *p_w3, *p_w4;
    if (!p_x512) {
        cudaGetSymbolAddress((void**)&p_x512, g_x512);
        cudaGetSymbolAddress((void**)&p_x256, g_x256);
        cudaGetSymbolAddress((void**)&p_x128, g_x128);
        cudaGetSymbolAddress((void**)&p_z,    g_z);
        cudaGetSymbolAddress((void**)&p_h1,   g_h1);
        cudaGetSymbolAddress((void**)&p_h2,   g_h2);
        cudaGetSymbolAddress((void**)&p_h3,   g_h3);
        cudaGetSymbolAddress((void**)&p_bw1,  g_bw1);
        cudaGetSymbolAddress((void**)&p_bw2,  g_bw2);
        cudaGetSymbolAddress((void**)&p_w0,   g_w0);
        cudaGetSymbolAddress((void**)&p_w1,   g_w1);
        cudaGetSymbolAddress((void**)&p_w2,   g_w2);
        cudaGetSymbolAddress((void**)&p_w3,   g_w3);
        cudaGetSymbolAddress((void**)&p_w4,   g_w4);
        cudaFuncSetAttribute((const void*)gemm_bf16<512, 1, false>,
                             cudaFuncAttributeMaxDynamicSharedMemorySize, SMEM_TM1);
        cudaFuncSetAttribute((const void*)gemm_bf16<256, 1, false>,
                             cudaFuncAttributeMaxDynamicSharedMemorySize, SMEM_TM1);
        cudaFuncSetAttribute((const void*)gemm_bf16<512, 1, true>,
                             cudaFuncAttributeMaxDynamicSharedMemorySize, SMEM_TM1);
        cudaFuncSetAttribute((const void*)gemm_bf16<512, 2, false>,
                             cudaFuncAttributeMaxDynamicSharedMemorySize, SMEM_TM2);
        cudaFuncSetAttribute((const void*)gemm_bf16<1024, 2, false>,
                             cudaFuncAttributeMaxDynamicSharedMemorySize, SMEM_TM2);
    }

    float* outf = (float*)d_out;

    // 1: fused weight prep + output zero
    prep_weights<<<(SZ_ALL + 255) / 256, 256>>>(tw0, bw1, bw2, tw1, tw2, tw3, tw4, outf);

    // 2: bottom MLP layer 0
    bot0_kernel<<<BATCH / B0S, 512>>>(dense_x, bw0, bb0, p_x512);
    // 3,4: bottom GEMMs (TM=1, 3 CTAs/SM)
    gemm_bf16<512, 1, false><<<dim3(2, 256), 256, SMEM_TM1>>>(p_x512, p_bw1, bb1, p_x256, 256, nullptr, nullptr);
    gemm_bf16<256, 1, false><<<dim3(1, 256), 256, SMEM_TM1>>>(p_x256, p_bw2, bb2, p_x128, 128, nullptr, nullptr);

    // 5: gather + tensor-core interaction -> z[B,512] bf16
    interact_kernel<<<BATCH, 256>>>(p_x128, emb, lS_i, p_z);

    // 6..8: top MLP big layers (TM=2: B-reuse bound, proven config)
    gemm_bf16<512, 2, false> <<<dim3(8, 128), 256, SMEM_TM2>>>(p_z,  p_w0, tb0, p_h1, 1024, nullptr, nullptr);
    gemm_bf16<1024, 2, false><<<dim3(8, 128), 256, SMEM_TM2>>>(p_h1, p_w1, tb1, p_h2, 1024, nullptr, nullptr);
    gemm_bf16<1024, 2, false><<<dim3(4, 128), 256, SMEM_TM2>>>(p_h2, p_w2, tb2, p_h3, 512, nullptr, nullptr);

    // 9: top3 GEMM fused with final dot (atomicAdd into outf), TM=1 3 CTAs/SM
    gemm_bf16<512, 1, true><<<dim3(2, 256), 256, SMEM_TM1>>>(p_h3, p_w3, tb3, nullptr, 256, outf, p_w4);

    // 10: sigmoid
    sigmoid_out<<<BATCH / 256, 256>>>(outf, tb4);
}